// round 3
// baseline (speedup 1.0000x reference)
#include <cuda_runtime.h>
#include <cstdint>

// Problem constants
#define BATCH   2
#define SEQ     2048
#define HEADS   16
#define DH      64
#define DIM     1024
#define INNER3  3072
#define NBLK    128    // sequence blocks (SEQ/16)
#define BLK     16

// Scratch (no allocations allowed -> device globals)
__device__ float g_qkv [(size_t)BATCH * SEQ * INNER3];  // [b*n, 3072]: q|k|v, each h*64+d
__device__ float g_attn[(size_t)BATCH * SEQ * DIM];     // [b*n, h*64+d]

// ---------------------------------------------------------------------------
// SGEMM: C[M,N] = A[M,K] @ B[K,N] (+bias), row-major, M%128==0, N%128==0, K%16==0
// 128x128 block tile, BK=16, 256 threads, 8x8 micro-tile per thread.
// ---------------------------------------------------------------------------
template <bool HAS_BIAS>
__device__ __forceinline__ void sgemm_body(int M, int N, int K,
                                           const float* __restrict__ A,
                                           const float* __restrict__ Bm,
                                           const float* __restrict__ bias,
                                           float* __restrict__ C)
{
    const int BM = 128, BN = 128, BK = 16;
    const int LDA = BM + 4;                 // 132: padded, keeps 16B alignment
    __shared__ float As[BK * (BM + 4)];     // transposed A tile: As[k][m]
    __shared__ float Bs[BK * BN];           // Bs[k][n]

    const int tid = threadIdx.x;            // 0..255
    const int tx  = tid & 15;               // micro-tile col group
    const int ty  = tid >> 4;               // micro-tile row group
    const int bn0 = blockIdx.x * BN;
    const int bm0 = blockIdx.y * BM;

    float acc[8][8];
    #pragma unroll
    for (int i = 0; i < 8; i++)
        #pragma unroll
        for (int j = 0; j < 8; j++) acc[i][j] = 0.f;

    for (int k0 = 0; k0 < K; k0 += BK) {
        // Load A tile (128x16) as 512 float4, store transposed into As[k][m]
        #pragma unroll
        for (int it = 0; it < 2; it++) {
            int idx  = tid + it * 256;          // 0..511
            int arow = idx >> 2;                // 0..127
            int avec = idx & 3;                 // 0..3 (float4 within row)
            float4 v = *(const float4*)(A + (size_t)(bm0 + arow) * K + k0 + avec * 4);
            As[(avec * 4 + 0) * LDA + arow] = v.x;
            As[(avec * 4 + 1) * LDA + arow] = v.y;
            As[(avec * 4 + 2) * LDA + arow] = v.z;
            As[(avec * 4 + 3) * LDA + arow] = v.w;
        }
        // Load B tile (16x128) as 512 float4
        #pragma unroll
        for (int it = 0; it < 2; it++) {
            int idx  = tid + it * 256;
            int brow = idx >> 5;                // 0..15
            int bvec = idx & 31;                // 0..31
            *(float4*)(Bs + brow * BN + bvec * 4) =
                *(const float4*)(Bm + (size_t)(k0 + brow) * N + bn0 + bvec * 4);
        }
        __syncthreads();

        #pragma unroll
        for (int k = 0; k < BK; k++) {
            float a[8], b[8];
            #pragma unroll
            for (int i = 0; i < 8; i += 4) {
                float4 t = *(const float4*)(As + k * LDA + ty * 8 + i);
                a[i] = t.x; a[i+1] = t.y; a[i+2] = t.z; a[i+3] = t.w;
            }
            #pragma unroll
            for (int i = 0; i < 8; i += 4) {
                float4 t = *(const float4*)(Bs + k * BN + tx * 8 + i);
                b[i] = t.x; b[i+1] = t.y; b[i+2] = t.z; b[i+3] = t.w;
            }
            #pragma unroll
            for (int i = 0; i < 8; i++)
                #pragma unroll
                for (int j = 0; j < 8; j++)
                    acc[i][j] += a[i] * b[j];
        }
        __syncthreads();
    }

    // Epilogue
    #pragma unroll
    for (int i = 0; i < 8; i++) {
        int row = bm0 + ty * 8 + i;
        #pragma unroll
        for (int j = 0; j < 8; j += 4) {
            int col = bn0 + tx * 8 + j;
            float4 v;
            v.x = acc[i][j + 0];
            v.y = acc[i][j + 1];
            v.z = acc[i][j + 2];
            v.w = acc[i][j + 3];
            if (HAS_BIAS) {
                v.x += bias[col + 0];
                v.y += bias[col + 1];
                v.z += bias[col + 2];
                v.w += bias[col + 3];
            }
            *(float4*)(C + (size_t)row * N + col) = v;
        }
    }
}

__global__ __launch_bounds__(256) void qkv_gemm_kernel(const float* __restrict__ x,
                                                       const float* __restrict__ w_qkv)
{
    sgemm_body<false>(BATCH * SEQ, INNER3, DIM, x, w_qkv, nullptr, g_qkv);
}

__global__ __launch_bounds__(256) void out_gemm_kernel(const float* __restrict__ w_out,
                                                       const float* __restrict__ b_out,
                                                       float* __restrict__ out)
{
    sgemm_body<true>(BATCH * SEQ, DIM, DIM, g_attn, w_out, b_out, out);
}

// ---------------------------------------------------------------------------
// Block-sparse causal attention.
// grid = (NBLK=128 query blocks, HEADS=16, BATCH=2), 256 threads.
// Each CTA: 16-row query block, online softmax over allowed 16x16 key blocks.
// Thread t: r = t>>4 (query row), c = t&15 (score col / 4-wide output group).
// ---------------------------------------------------------------------------
__global__ __launch_bounds__(256) void sparse_attn_kernel(const void* __restrict__ layout_raw)
{
    const int qb = blockIdx.x;
    const int h  = blockIdx.y;
    const int b  = blockIdx.z;

    const int t  = threadIdx.x;
    const int r  = t >> 4;       // 0..15
    const int c  = t & 15;       // 0..15
    const int c0 = c * 4;        // output col group

    __shared__ float qs[16 * 65];
    __shared__ float ks[16 * 65];
    __shared__ float vs[16 * 65];
    __shared__ float Ss[16 * 17];
    __shared__ float Ps[16 * 17];
    __shared__ float msh[16], mnw[16], lsh[16];

    // Layout dtype auto-detect. layout[1][0] (global column 0, kept by tril)
    // is deterministically true. If the buffer is bool/uint8, byte 128 == 1;
    // if it is int32/float32 (elem 32 = layout[0][32] = false), byte 128 == 0.
    const unsigned char* lb = (const unsigned char*)layout_raw;
    const bool is_u8 = (lb[128] != 0);
    const uint32_t* lw = (const uint32_t*)layout_raw;

    const float* base = g_qkv + (size_t)b * SEQ * INNER3;

    // Load Q tile [16,64] -> qs (pad 65); one float4 per thread.
    {
        float4 v = *(const float4*)(base + (size_t)(qb * BLK + r) * INNER3 + h * DH + c0);
        qs[r * 65 + c0 + 0] = v.x;
        qs[r * 65 + c0 + 1] = v.y;
        qs[r * 65 + c0 + 2] = v.z;
        qs[r * 65 + c0 + 3] = v.w;
    }
    if (t < 16) { msh[t] = -1e30f; lsh[t] = 0.f; }

    float o0 = 0.f, o1 = 0.f, o2 = 0.f, o3 = 0.f;
    const float scale = 0.125f;  // 1/sqrt(64)

    for (int jb = 0; jb <= qb; jb++) {
        bool allowed = is_u8 ? (lb[qb * NBLK + jb] != 0)
                             : (lw[qb * NBLK + jb] != 0u);
        if (!allowed) continue;

        __syncthreads();  // prior iteration done with ks/vs/Ps; msh/lsh updated

        // Load K and V tiles [16,64] -> ks/vs
        {
            const float* kp = base + (size_t)(jb * BLK + r) * INNER3 + DIM + h * DH + c0;
            float4 kv = *(const float4*)kp;
            ks[r * 65 + c0 + 0] = kv.x;
            ks[r * 65 + c0 + 1] = kv.y;
            ks[r * 65 + c0 + 2] = kv.z;
            ks[r * 65 + c0 + 3] = kv.w;
            const float* vp = base + (size_t)(jb * BLK + r) * INNER3 + 2 * DIM + h * DH + c0;
            float4 vv = *(const float4*)vp;
            vs[r * 65 + c0 + 0] = vv.x;
            vs[r * 65 + c0 + 1] = vv.y;
            vs[r * 65 + c0 + 2] = vv.z;
            vs[r * 65 + c0 + 3] = vv.w;
        }
        __syncthreads();

        // Scores: thread (r,c) computes S[r][c] = scale * <q_r, k_c>
        float s = 0.f;
        {
            const float* qp = qs + r * 65;
            const float* kp = ks + c * 65;
            #pragma unroll
            for (int d = 0; d < DH; d++) s += qp[d] * kp[d];
        }
        s *= scale;
        if (jb == qb && c > r) s = -1e30f;   // causal within diagonal block
        Ss[r * 17 + c] = s;
        __syncthreads();

        // Per-row max and new running max
        if (t < 16) {
            float mx = Ss[t * 17 + 0];
            #pragma unroll
            for (int j = 1; j < 16; j++) mx = fmaxf(mx, Ss[t * 17 + j]);
            mnw[t] = fmaxf(msh[t], mx);
        }
        __syncthreads();

        const float mn   = mnw[r];
        const float corr = __expf(msh[r] - mn);
        const float p    = __expf(s - mn);
        Ps[r * 17 + c]   = p;
        o0 *= corr; o1 *= corr; o2 *= corr; o3 *= corr;
        __syncthreads();  // Ps complete; all msh reads done

        // Row sum + running-denominator update (one thread per row)
        if (t < 16) {
            float sum = 0.f;
            #pragma unroll
            for (int j = 0; j < 16; j++) sum += Ps[t * 17 + j];
            lsh[t] = lsh[t] * __expf(msh[t] - mnw[t]) + sum;
            msh[t] = mnw[t];
        }

        // O[r][c0..c0+3] += P[r][:] @ V[:, c0..c0+3]
        #pragma unroll
        for (int j = 0; j < 16; j++) {
            const float  pj = Ps[r * 17 + j];
            const float* vp = vs + j * 65 + c0;
            o0 += pj * vp[0];
            o1 += pj * vp[1];
            o2 += pj * vp[2];
            o3 += pj * vp[3];
        }
    }

    __syncthreads();
    const float inv = 1.f / lsh[r];
    float* outp = g_attn + (size_t)(b * SEQ + qb * BLK + r) * DIM + h * DH + c0;
    float4 ov;
    ov.x = o0 * inv; ov.y = o1 * inv; ov.z = o2 * inv; ov.w = o3 * inv;
    *(float4*)outp = ov;
}

// ---------------------------------------------------------------------------
// Inputs (metadata order = setup_inputs order):
//   0: x      [2,2048,1024] f32      1: w_qkv  [1024,3072] f32
//   2: w_out  [1024,1024]  f32       3: b_out  [1024]      f32
//   4: layout [128,128]    bool (dtype auto-detected in-kernel)
// Output: [2,2048,1024] f32
// ---------------------------------------------------------------------------
extern "C" void kernel_launch(void* const* d_in, const int* in_sizes, int n_in,
                              void* d_out, int out_size)
{
    const float* x     = (const float*)d_in[0];
    const float* w_qkv = (const float*)d_in[1];
    const float* w_out = (const float*)d_in[2];
    const float* b_out = (const float*)d_in[3];
    const void*  layout = d_in[4];
    float* out = (float*)d_out;

    // 1) QKV projection: [4096,1024] @ [1024,3072] -> g_qkv
    {
        dim3 grid(INNER3 / 128, (BATCH * SEQ) / 128);
        qkv_gemm_kernel<<<grid, 256>>>(x, w_qkv);
    }
    // 2) Block-sparse causal attention -> g_attn
    {
        dim3 grid(NBLK, HEADS, BATCH);
        sparse_attn_kernel<<<grid, 256>>>(layout);
    }
    // 3) Output projection + bias: [4096,1024] @ [1024,1024] + b -> out
    {
        dim3 grid(DIM / 128, (BATCH * SEQ) / 128);
        out_gemm_kernel<<<grid, 256>>>(w_out, b_out, out);
    }
}

// round 4
// speedup vs baseline: 1.3067x; 1.3067x over previous
#include <cuda_runtime.h>
#include <cstdint>

// Problem constants
#define BATCH   2
#define SEQ     2048
#define HEADS   16
#define DH      64
#define DIM     1024
#define INNER3  3072
#define NBLK    128    // sequence blocks (SEQ/16)
#define BLK     16

// Scratch (no allocations allowed -> device globals)
__device__ float g_qkv [(size_t)BATCH * SEQ * INNER3];  // [b*n, 3072]: q|k|v, each h*64+d
__device__ float g_attn[(size_t)BATCH * SEQ * DIM];     // [b*n, h*64+d]

// ---------------------------------------------------------------------------
// Async-copy helpers
// ---------------------------------------------------------------------------
__device__ __forceinline__ uint32_t smem_u32(const void* p) {
    uint32_t a;
    asm("{ .reg .u64 t; cvta.to.shared.u64 t, %1; cvt.u32.u64 %0, t; }"
        : "=r"(a) : "l"(p));
    return a;
}
__device__ __forceinline__ void cp_async16(uint32_t dst, const void* src) {
    asm volatile("cp.async.cg.shared.global [%0], [%1], 16;" :: "r"(dst), "l"(src));
}
__device__ __forceinline__ void cp_commit() {
    asm volatile("cp.async.commit_group;");
}
__device__ __forceinline__ void cp_wait0() {
    asm volatile("cp.async.wait_group 0;" ::: "memory");
}

// ---------------------------------------------------------------------------
// SGEMM: C[M,N] = A[M,K] @ B[K,N] (+bias), row-major, M%128==0, N%128==0, K%16==0
// 128x128 tile, BK=16, 256 threads, 8x8 micro-tile. Double-buffered smem:
// B via cp.async, A via register-staged transpose. One syncthreads per K-iter.
// ---------------------------------------------------------------------------
template <bool HAS_BIAS>
__device__ __forceinline__ void sgemm_body(int M, int N, int K,
                                           const float* __restrict__ A,
                                           const float* __restrict__ Bm,
                                           const float* __restrict__ bias,
                                           float* __restrict__ C)
{
    const int BM = 128, BN = 128, BK = 16;
    const int LDA = BM + 4;                     // 132: padded, 16B-aligned rows
    __shared__ float As[2][BK * (BM + 4)];      // transposed A tile: As[k][m]
    __shared__ float Bs[2][BK * BN];            // Bs[k][n]

    const int tid = threadIdx.x;                // 0..255
    const int tx  = tid & 15;
    const int ty  = tid >> 4;
    const int bn0 = blockIdx.x * BN;
    const int bm0 = blockIdx.y * BM;

    // A load mapping: 512 float4; thread handles idx = tid, tid+256
    const int arow0 = tid >> 2;                 // 0..63
    const int avec0 = tid & 3;
    const int arow1 = (tid + 256) >> 2;         // 64..127
    const int avec1 = avec0;
    // B load mapping: 512 float4
    const int brow0 = tid >> 5;                 // 0..7
    const int bvec0 = tid & 31;
    const int brow1 = brow0 + 8;                // 8..15
    const int bvec1 = bvec0;

    float4 aReg0, aReg1;
    float acc[8][8];
    #pragma unroll
    for (int i = 0; i < 8; i++)
        #pragma unroll
        for (int j = 0; j < 8; j++) acc[i][j] = 0.f;

    // ---- prologue: tile 0 ----
    {
        cp_async16(smem_u32(&Bs[0][brow0 * BN + bvec0 * 4]),
                   Bm + (size_t)brow0 * N + bn0 + bvec0 * 4);
        cp_async16(smem_u32(&Bs[0][brow1 * BN + bvec1 * 4]),
                   Bm + (size_t)brow1 * N + bn0 + bvec1 * 4);
        cp_commit();
        aReg0 = *(const float4*)(A + (size_t)(bm0 + arow0) * K + avec0 * 4);
        aReg1 = *(const float4*)(A + (size_t)(bm0 + arow1) * K + avec1 * 4);
        As[0][(avec0 * 4 + 0) * LDA + arow0] = aReg0.x;
        As[0][(avec0 * 4 + 1) * LDA + arow0] = aReg0.y;
        As[0][(avec0 * 4 + 2) * LDA + arow0] = aReg0.z;
        As[0][(avec0 * 4 + 3) * LDA + arow0] = aReg0.w;
        As[0][(avec1 * 4 + 0) * LDA + arow1] = aReg1.x;
        As[0][(avec1 * 4 + 1) * LDA + arow1] = aReg1.y;
        As[0][(avec1 * 4 + 2) * LDA + arow1] = aReg1.z;
        As[0][(avec1 * 4 + 3) * LDA + arow1] = aReg1.w;
        cp_wait0();
    }
    __syncthreads();

    int cur = 0;
    for (int k0 = 0; k0 < K; k0 += BK) {
        const int nxt = cur ^ 1;
        const bool has_next = (k0 + BK) < K;
        if (has_next) {
            const int kn = k0 + BK;
            cp_async16(smem_u32(&Bs[nxt][brow0 * BN + bvec0 * 4]),
                       Bm + (size_t)(kn + brow0) * N + bn0 + bvec0 * 4);
            cp_async16(smem_u32(&Bs[nxt][brow1 * BN + bvec1 * 4]),
                       Bm + (size_t)(kn + brow1) * N + bn0 + bvec1 * 4);
            cp_commit();
            aReg0 = *(const float4*)(A + (size_t)(bm0 + arow0) * K + kn + avec0 * 4);
            aReg1 = *(const float4*)(A + (size_t)(bm0 + arow1) * K + kn + avec1 * 4);
        }

        const float* __restrict__ Asc = As[cur];
        const float* __restrict__ Bsc = Bs[cur];
        #pragma unroll
        for (int k = 0; k < BK; k++) {
            float a[8], b[8];
            #pragma unroll
            for (int i = 0; i < 8; i += 4) {
                float4 t = *(const float4*)(Asc + k * LDA + ty * 8 + i);
                a[i] = t.x; a[i+1] = t.y; a[i+2] = t.z; a[i+3] = t.w;
            }
            #pragma unroll
            for (int i = 0; i < 8; i += 4) {
                float4 t = *(const float4*)(Bsc + k * BN + tx * 8 + i);
                b[i] = t.x; b[i+1] = t.y; b[i+2] = t.z; b[i+3] = t.w;
            }
            #pragma unroll
            for (int i = 0; i < 8; i++)
                #pragma unroll
                for (int j = 0; j < 8; j++)
                    acc[i][j] += a[i] * b[j];
        }

        if (has_next) {
            As[nxt][(avec0 * 4 + 0) * LDA + arow0] = aReg0.x;
            As[nxt][(avec0 * 4 + 1) * LDA + arow0] = aReg0.y;
            As[nxt][(avec0 * 4 + 2) * LDA + arow0] = aReg0.z;
            As[nxt][(avec0 * 4 + 3) * LDA + arow0] = aReg0.w;
            As[nxt][(avec1 * 4 + 0) * LDA + arow1] = aReg1.x;
            As[nxt][(avec1 * 4 + 1) * LDA + arow1] = aReg1.y;
            As[nxt][(avec1 * 4 + 2) * LDA + arow1] = aReg1.z;
            As[nxt][(avec1 * 4 + 3) * LDA + arow1] = aReg1.w;
            cp_wait0();
        }
        __syncthreads();
        cur = nxt;
    }

    // Epilogue
    #pragma unroll
    for (int i = 0; i < 8; i++) {
        int row = bm0 + ty * 8 + i;
        #pragma unroll
        for (int j = 0; j < 8; j += 4) {
            int col = bn0 + tx * 8 + j;
            float4 v;
            v.x = acc[i][j + 0];
            v.y = acc[i][j + 1];
            v.z = acc[i][j + 2];
            v.w = acc[i][j + 3];
            if (HAS_BIAS) {
                v.x += bias[col + 0];
                v.y += bias[col + 1];
                v.z += bias[col + 2];
                v.w += bias[col + 3];
            }
            *(float4*)(C + (size_t)row * N + col) = v;
        }
    }
}

__global__ __launch_bounds__(256, 2) void qkv_gemm_kernel(const float* __restrict__ x,
                                                          const float* __restrict__ w_qkv)
{
    sgemm_body<false>(BATCH * SEQ, INNER3, DIM, x, w_qkv, nullptr, g_qkv);
}

__global__ __launch_bounds__(256, 2) void out_gemm_kernel(const float* __restrict__ w_out,
                                                          const float* __restrict__ b_out,
                                                          float* __restrict__ out)
{
    sgemm_body<true>(BATCH * SEQ, DIM, DIM, g_attn, w_out, b_out, out);
}

// ---------------------------------------------------------------------------
// Block-sparse causal attention.
// grid = (NBLK, HEADS, BATCH), 128 threads.
// Thread t: c = t&15 (key column), rp = t>>4 (row pair 0..7) -> rows {2rp, 2rp+1}.
// Online softmax via warp shuffles; all smem accesses are float4 with stride 68.
// ---------------------------------------------------------------------------
#define SP 68   // smem row stride in floats: 272B (16B aligned), 2-way max conflict

__global__ __launch_bounds__(128) void sparse_attn_kernel(const void* __restrict__ layout_raw)
{
    const int qb = blockIdx.x;
    const int h  = blockIdx.y;
    const int b  = blockIdx.z;

    const int t  = threadIdx.x;       // 0..127
    const int c  = t & 15;
    const int rp = t >> 4;            // 0..7
    const int r0 = rp * 2;
    const int r1 = rp * 2 + 1;
    const int c0 = c * 4;
    const int lanebase = t & 16;      // bit 4 of lane id within warp

    __shared__ float qs[16 * SP];
    __shared__ float ks[16 * SP];
    __shared__ float vs[16 * SP];

    // Layout dtype auto-detect: layout[1][0] is deterministically True
    // (global column 0 survives tril). byte 128 == 1 iff buffer is bool/uint8.
    const unsigned char* lb = (const unsigned char*)layout_raw;
    const bool is_u8 = (lb[128] != 0);
    const uint32_t* lw = (const uint32_t*)layout_raw;

    const float* base = g_qkv + (size_t)b * SEQ * INNER3;

    // Load Q tile [16,64]: 256 float4, 128 threads -> 2 each.
    #pragma unroll
    for (int it = 0; it < 2; it++) {
        int f = t + it * 128;
        int row = f >> 4, cc = f & 15;
        float4 v = *(const float4*)(base + (size_t)(qb * BLK + row) * INNER3 + h * DH + cc * 4);
        *(float4*)(qs + row * SP + cc * 4) = v;
    }

    float m0 = -1e30f, l0 = 0.f, m1 = -1e30f, l1 = 0.f;
    float4 o0 = make_float4(0.f, 0.f, 0.f, 0.f);
    float4 o1 = make_float4(0.f, 0.f, 0.f, 0.f);
    const float scale = 0.125f;   // 1/sqrt(64)

    for (int jb = 0; jb <= qb; jb++) {
        bool allowed = is_u8 ? (lb[qb * NBLK + jb] != 0)
                             : (lw[qb * NBLK + jb] != 0u);
        if (!allowed) continue;

        __syncthreads();   // previous iteration done reading ks/vs

        // Load K and V tiles [16,64] each
        #pragma unroll
        for (int it = 0; it < 2; it++) {
            int f = t + it * 128;
            int row = f >> 4, cc = f & 15;
            const float* rowp = base + (size_t)(jb * BLK + row) * INNER3 + h * DH + cc * 4;
            *(float4*)(ks + row * SP + cc * 4) = *(const float4*)(rowp + DIM);
            *(float4*)(vs + row * SP + cc * 4) = *(const float4*)(rowp + 2 * DIM);
        }
        __syncthreads();

        // Scores: thread computes S[r0][c] and S[r1][c]; K column read once.
        float s0 = 0.f, s1 = 0.f;
        {
            const float4* kp = (const float4*)(ks + c  * SP);
            const float4* q0 = (const float4*)(qs + r0 * SP);
            const float4* q1 = (const float4*)(qs + r1 * SP);
            #pragma unroll
            for (int d = 0; d < 16; d++) {
                float4 kk = kp[d];
                float4 a0 = q0[d];
                float4 a1 = q1[d];
                s0 += a0.x * kk.x + a0.y * kk.y + a0.z * kk.z + a0.w * kk.w;
                s1 += a1.x * kk.x + a1.y * kk.y + a1.z * kk.z + a1.w * kk.w;
            }
        }
        s0 *= scale;
        s1 *= scale;
        if (jb == qb) {                     // causal within diagonal block
            if (c > r0) s0 = -1e30f;
            if (c > r1) s1 = -1e30f;
        }

        // Row max over the 16-lane column group
        float mr0 = s0, mr1 = s1;
        #pragma unroll
        for (int k = 1; k < 16; k <<= 1) {
            mr0 = fmaxf(mr0, __shfl_xor_sync(0xffffffffu, mr0, k, 32));
            mr1 = fmaxf(mr1, __shfl_xor_sync(0xffffffffu, mr1, k, 32));
        }
        float mn0 = fmaxf(m0, mr0);
        float mn1 = fmaxf(m1, mr1);
        float p0  = __expf(s0 - mn0);
        float p1  = __expf(s1 - mn1);
        float cr0 = __expf(m0 - mn0);
        float cr1 = __expf(m1 - mn1);

        // Row sum
        float sm0 = p0, sm1 = p1;
        #pragma unroll
        for (int k = 1; k < 16; k <<= 1) {
            sm0 += __shfl_xor_sync(0xffffffffu, sm0, k, 32);
            sm1 += __shfl_xor_sync(0xffffffffu, sm1, k, 32);
        }
        l0 = l0 * cr0 + sm0;  m0 = mn0;
        l1 = l1 * cr1 + sm1;  m1 = mn1;
        o0.x *= cr0; o0.y *= cr0; o0.z *= cr0; o0.w *= cr0;
        o1.x *= cr1; o1.y *= cr1; o1.z *= cr1; o1.w *= cr1;

        // O[r][c0..c0+3] += P[r][:] @ V[:, c0..c0+3]; P broadcast via shuffle.
        #pragma unroll
        for (int j = 0; j < 16; j++) {
            float pj0 = __shfl_sync(0xffffffffu, p0, lanebase | j, 32);
            float pj1 = __shfl_sync(0xffffffffu, p1, lanebase | j, 32);
            float4 vv = *(const float4*)(vs + j * SP + c0);
            o0.x += pj0 * vv.x; o0.y += pj0 * vv.y; o0.z += pj0 * vv.z; o0.w += pj0 * vv.w;
            o1.x += pj1 * vv.x; o1.y += pj1 * vv.y; o1.z += pj1 * vv.z; o1.w += pj1 * vv.w;
        }
    }

    // Write output rows (l > 0 guaranteed: diagonal block always allowed)
    const float inv0 = 1.f / l0;
    const float inv1 = 1.f / l1;
    float* op0 = g_attn + (size_t)(b * SEQ + qb * BLK + r0) * DIM + h * DH + c0;
    float* op1 = g_attn + (size_t)(b * SEQ + qb * BLK + r1) * DIM + h * DH + c0;
    *(float4*)op0 = make_float4(o0.x * inv0, o0.y * inv0, o0.z * inv0, o0.w * inv0);
    *(float4*)op1 = make_float4(o1.x * inv1, o1.y * inv1, o1.z * inv1, o1.w * inv1);
}

// ---------------------------------------------------------------------------
// Inputs (metadata order = setup_inputs order):
//   0: x      [2,2048,1024] f32      1: w_qkv  [1024,3072] f32
//   2: w_out  [1024,1024]  f32       3: b_out  [1024]      f32
//   4: layout [128,128]    bool (dtype auto-detected in-kernel)
// Output: [2,2048,1024] f32
// ---------------------------------------------------------------------------
extern "C" void kernel_launch(void* const* d_in, const int* in_sizes, int n_in,
                              void* d_out, int out_size)
{
    const float* x      = (const float*)d_in[0];
    const float* w_qkv  = (const float*)d_in[1];
    const float* w_out  = (const float*)d_in[2];
    const float* b_out  = (const float*)d_in[3];
    const void*  layout = d_in[4];
    float* out = (float*)d_out;

    // 1) QKV projection: [4096,1024] @ [1024,3072] -> g_qkv
    {
        dim3 grid(INNER3 / 128, (BATCH * SEQ) / 128);
        qkv_gemm_kernel<<<grid, 256>>>(x, w_qkv);
    }
    // 2) Block-sparse causal attention -> g_attn
    {
        dim3 grid(NBLK, HEADS, BATCH);
        sparse_attn_kernel<<<grid, 128>>>(layout);
    }
    // 3) Output projection + bias: [4096,1024] @ [1024,1024] + b -> out
    {
        dim3 grid(DIM / 128, (BATCH * SEQ) / 128);
        out_gemm_kernel<<<grid, 256>>>(w_out, b_out, out);
    }
}

// round 8
// speedup vs baseline: 2.2387x; 1.7132x over previous
#include <cuda_runtime.h>
#include <cuda_bf16.h>
#include <cstdint>

// Problem constants
#define BATCH   2
#define SEQ     2048
#define HEADS   16
#define DH      64
#define DIM     1024
#define INNER3  3072
#define NBLK    128
#define BLK     16
#define GK      1024        // K dim of both GEMMs

// Scratch (no allocations allowed -> device globals)
__device__ float g_qkv [(size_t)BATCH * SEQ * INNER3];  // [b*n, 3072]: q|k|v
__device__ float g_attn[(size_t)BATCH * SEQ * DIM];     // [b*n, h*64+d]
__device__ __align__(16) __nv_bfloat16 g_a_hi [(size_t)BATCH * SEQ * DIM];   // split A (x, then attn)
__device__ __align__(16) __nv_bfloat16 g_a_lo [(size_t)BATCH * SEQ * DIM];
__device__ __align__(16) __nv_bfloat16 g_wq_hi[(size_t)INNER3 * DIM];        // w_qkv^T split [N,K]
__device__ __align__(16) __nv_bfloat16 g_wq_lo[(size_t)INNER3 * DIM];
__device__ __align__(16) __nv_bfloat16 g_wo_hi[(size_t)DIM * DIM];           // w_out^T split [N,K]
__device__ __align__(16) __nv_bfloat16 g_wo_lo[(size_t)DIM * DIM];

// ---------------------------------------------------------------------------
// Async-copy helpers
// ---------------------------------------------------------------------------
__device__ __forceinline__ uint32_t smem_u32(const void* p) {
    uint32_t a;
    asm("{ .reg .u64 t; cvta.to.shared.u64 t, %1; cvt.u32.u64 %0, t; }"
        : "=r"(a) : "l"(p));
    return a;
}
__device__ __forceinline__ void cp_async16(uint32_t dst, const void* src) {
    asm volatile("cp.async.cg.shared.global [%0], [%1], 16;" :: "r"(dst), "l"(src));
}
__device__ __forceinline__ void cp_commit() {
    asm volatile("cp.async.commit_group;");
}
__device__ __forceinline__ void cp_wait0() {
    asm volatile("cp.async.wait_group 0;" ::: "memory");
}
__device__ __forceinline__ void mma_bf16(float c[4], uint32_t a0, uint32_t a1,
                                         uint32_t a2, uint32_t a3,
                                         uint32_t b0, uint32_t b1) {
    asm volatile(
        "mma.sync.aligned.m16n8k16.row.col.f32.bf16.bf16.f32 "
        "{%0,%1,%2,%3}, {%4,%5,%6,%7}, {%8,%9}, {%0,%1,%2,%3};"
        : "+f"(c[0]), "+f"(c[1]), "+f"(c[2]), "+f"(c[3])
        : "r"(a0), "r"(a1), "r"(a2), "r"(a3), "r"(b0), "r"(b1));
}

// ---------------------------------------------------------------------------
// HMMA bf16-split GEMM: C[M,Ntot] = A[M,GK] @ Bt[Ntot,GK]^T (+bias)
// CTA tile 128x128, BK=32, 256 threads = 8 warps in 2(m) x 4(n), warp tile 64x32.
// 3-way split per k16 step: AhBh + AhBl + AlBh (drops AlBl, ~2^-16 relative).
// Smem rows padded to 40 bf16 (80B) -> conflict-free fragment LDS.
// Double-buffered via cp.async. Dynamic smem = 81920 B.
// ---------------------------------------------------------------------------
#define BK      32
#define ROWP    40                         // padded row length in bf16
#define ARR_B   (128 * ROWP * 2)           // 10240 bytes per array
#define STG_B   (4 * ARR_B)                // 40960 bytes per stage
#define SM_GEMM (2 * STG_B)                // 81920

template <bool HAS_BIAS>
__device__ __forceinline__ void hmma_gemm_body(
    const __nv_bfloat16* __restrict__ Ahi, const __nv_bfloat16* __restrict__ Alo,
    const __nv_bfloat16* __restrict__ Bhi, const __nv_bfloat16* __restrict__ Blo,
    const float* __restrict__ bias, float* __restrict__ C, int Ntot)
{
    extern __shared__ char dsm[];
    const uint32_t smb = smem_u32(dsm);

    const int t    = threadIdx.x;          // 0..255
    const int lane = t & 31;
    const int wid  = t >> 5;               // 0..7
    const int wm   = wid >> 2;             // 0..1
    const int wn   = wid & 3;              // 0..3
    const int gid  = lane >> 2;            // 0..7
    const int tg   = lane & 3;             // 0..3
    const int bn0  = blockIdx.x * 128;
    const int bm0  = blockIdx.y * 128;

    float acc[4][4][4];
    #pragma unroll
    for (int i = 0; i < 4; i++)
        #pragma unroll
        for (int j = 0; j < 4; j++)
            #pragma unroll
            for (int k = 0; k < 4; k++) acc[i][j][k] = 0.f;

    const __nv_bfloat16* gA[2] = { Ahi + (size_t)bm0 * GK, Alo + (size_t)bm0 * GK };
    const __nv_bfloat16* gB[2] = { Bhi + (size_t)bn0 * GK, Blo + (size_t)bn0 * GK };

    // Issue all cp.async for one stage: 4 arrays x 512 16B-chunks
    auto load_stage = [&](int stage, int kofs) {
        const uint32_t base = smb + stage * STG_B;
        #pragma unroll
        for (int arr = 0; arr < 4; arr++) {          // 0:Ah 1:Al 2:Bh 3:Bl
            const __nv_bfloat16* src = (arr < 2) ? gA[arr] : gB[arr - 2];
            const uint32_t dst0 = base + arr * ARR_B;
            #pragma unroll
            for (int i = 0; i < 2; i++) {
                int idx = t + i * 256;               // 0..511
                int row = idx >> 2;                  // 0..127
                int c16 = idx & 3;                   // 0..3
                cp_async16(dst0 + row * (ROWP * 2) + c16 * 16,
                           src + (size_t)row * GK + kofs + c16 * 8);
            }
        }
        cp_commit();
    };

    load_stage(0, 0);
    cp_wait0();
    __syncthreads();

    int cur = 0;
    for (int kc = 0; kc < GK / BK; kc++) {
        const int nxt = cur ^ 1;
        if (kc + 1 < GK / BK) load_stage(nxt, (kc + 1) * BK);

        const uint32_t* Ah = (const uint32_t*)(dsm + cur * STG_B + 0 * ARR_B);
        const uint32_t* Al = (const uint32_t*)(dsm + cur * STG_B + 1 * ARR_B);
        const uint32_t* Bh = (const uint32_t*)(dsm + cur * STG_B + 2 * ARR_B);
        const uint32_t* Bl = (const uint32_t*)(dsm + cur * STG_B + 3 * ARR_B);

        #pragma unroll
        for (int ks = 0; ks < 2; ks++) {             // two k16 steps per BK=32
            const int ko = ks * 8 + tg;              // u32 column offset
            uint32_t ah[4][4], al[4][4], bh[4][2], bl[4][2];
            #pragma unroll
            for (int mf = 0; mf < 4; mf++) {
                int rb = (wm * 64 + mf * 16 + gid) * (ROWP / 2) + ko;
                ah[mf][0] = Ah[rb];
                ah[mf][1] = Ah[rb + 8 * (ROWP / 2)];
                ah[mf][2] = Ah[rb + 4];
                ah[mf][3] = Ah[rb + 8 * (ROWP / 2) + 4];
                al[mf][0] = Al[rb];
                al[mf][1] = Al[rb + 8 * (ROWP / 2)];
                al[mf][2] = Al[rb + 4];
                al[mf][3] = Al[rb + 8 * (ROWP / 2) + 4];
            }
            #pragma unroll
            for (int nf = 0; nf < 4; nf++) {
                int nb = (wn * 32 + nf * 8 + gid) * (ROWP / 2) + ko;
                bh[nf][0] = Bh[nb];
                bh[nf][1] = Bh[nb + 4];
                bl[nf][0] = Bl[nb];
                bl[nf][1] = Bl[nb + 4];
            }
            #pragma unroll
            for (int mf = 0; mf < 4; mf++)
                #pragma unroll
                for (int nf = 0; nf < 4; nf++) {
                    mma_bf16(acc[mf][nf], ah[mf][0], ah[mf][1], ah[mf][2], ah[mf][3],
                             bh[nf][0], bh[nf][1]);
                    mma_bf16(acc[mf][nf], ah[mf][0], ah[mf][1], ah[mf][2], ah[mf][3],
                             bl[nf][0], bl[nf][1]);
                    mma_bf16(acc[mf][nf], al[mf][0], al[mf][1], al[mf][2], al[mf][3],
                             bh[nf][0], bh[nf][1]);
                }
        }

        cp_wait0();
        __syncthreads();
        cur = nxt;
    }

    // Epilogue: (c0,c1) -> row gid, cols tg*2..+1; (c2,c3) -> row gid+8
    #pragma unroll
    for (int mf = 0; mf < 4; mf++) {
        int row = bm0 + wm * 64 + mf * 16 + gid;
        #pragma unroll
        for (int nf = 0; nf < 4; nf++) {
            int col = bn0 + wn * 32 + nf * 8 + tg * 2;
            float bx = 0.f, by = 0.f;
            if (HAS_BIAS) { bx = bias[col]; by = bias[col + 1]; }
            float2 v0 = make_float2(acc[mf][nf][0] + bx, acc[mf][nf][1] + by);
            float2 v1 = make_float2(acc[mf][nf][2] + bx, acc[mf][nf][3] + by);
            *(float2*)(C + (size_t)row * Ntot + col)       = v0;
            *(float2*)(C + (size_t)(row + 8) * Ntot + col) = v1;
        }
    }
}

__global__ __launch_bounds__(256) void tc_gemm1_kernel()
{
    hmma_gemm_body<false>(g_a_hi, g_a_lo, g_wq_hi, g_wq_lo, nullptr, g_qkv, INNER3);
}

__global__ __launch_bounds__(256) void tc_gemm2_kernel(const float* __restrict__ bias,
                                                       float* __restrict__ out)
{
    hmma_gemm_body<true>(g_a_hi, g_a_lo, g_wo_hi, g_wo_lo, bias, out, DIM);
}

// ---------------------------------------------------------------------------
// fp32 -> (bf16 hi, bf16 lo) elementwise split. 4 elems/thread.
// ---------------------------------------------------------------------------
__device__ __forceinline__ void split_body(const float* __restrict__ src,
                                           __nv_bfloat16* __restrict__ hi,
                                           __nv_bfloat16* __restrict__ lo)
{
    const int i0 = (blockIdx.x * 256 + threadIdx.x) * 4;
    float4 v = *(const float4*)(src + i0);
    __nv_bfloat16 h0 = __float2bfloat16(v.x);
    __nv_bfloat16 h1 = __float2bfloat16(v.y);
    __nv_bfloat16 h2 = __float2bfloat16(v.z);
    __nv_bfloat16 h3 = __float2bfloat16(v.w);
    __nv_bfloat16 l0 = __float2bfloat16(v.x - __bfloat162float(h0));
    __nv_bfloat16 l1 = __float2bfloat16(v.y - __bfloat162float(h1));
    __nv_bfloat16 l2 = __float2bfloat16(v.z - __bfloat162float(h2));
    __nv_bfloat16 l3 = __float2bfloat16(v.w - __bfloat162float(h3));
    __nv_bfloat162 hh0; hh0.x = h0; hh0.y = h1;
    __nv_bfloat162 hh1; hh1.x = h2; hh1.y = h3;
    __nv_bfloat162 ll0; ll0.x = l0; ll0.y = l1;
    __nv_bfloat162 ll1; ll1.x = l2; ll1.y = l3;
    *(__nv_bfloat162*)(hi + i0)     = hh0;
    *(__nv_bfloat162*)(hi + i0 + 2) = hh1;
    *(__nv_bfloat162*)(lo + i0)     = ll0;
    *(__nv_bfloat162*)(lo + i0 + 2) = ll1;
}

__global__ __launch_bounds__(256) void split_x_kernel(const float* __restrict__ x)
{
    split_body(x, g_a_hi, g_a_lo);
}
__global__ __launch_bounds__(256) void split_attn_kernel()
{
    split_body(g_attn, g_a_hi, g_a_lo);
}

// ---------------------------------------------------------------------------
// Transpose + split: src [GK x N] fp32 -> dst_hi/lo [N x GK] bf16
// ---------------------------------------------------------------------------
__device__ __forceinline__ void tsp_body(const float* __restrict__ src,
                                         __nv_bfloat16* __restrict__ dhi,
                                         __nv_bfloat16* __restrict__ dlo, int N)
{
    __shared__ float tile[32][33];
    const int bx = blockIdx.x * 32;   // N offset
    const int by = blockIdx.y * 32;   // K offset
    const int tx = threadIdx.x & 31;
    const int ty = threadIdx.x >> 5;  // 0..7
    #pragma unroll
    for (int i = 0; i < 4; i++)
        tile[ty + i * 8][tx] = src[(size_t)(by + ty + i * 8) * N + bx + tx];
    __syncthreads();
    #pragma unroll
    for (int i = 0; i < 4; i++) {
        float v = tile[tx][ty + i * 8];
        __nv_bfloat16 h = __float2bfloat16(v);
        __nv_bfloat16 l = __float2bfloat16(v - __bfloat162float(h));
        size_t o = (size_t)(bx + ty + i * 8) * GK + by + tx;
        dhi[o] = h;
        dlo[o] = l;
    }
}

__global__ __launch_bounds__(256) void tsp_wq_kernel(const float* __restrict__ w)
{
    tsp_body(w, g_wq_hi, g_wq_lo, INNER3);
}
__global__ __launch_bounds__(256) void tsp_wo_kernel(const float* __restrict__ w)
{
    tsp_body(w, g_wo_hi, g_wo_lo, DIM);
}

// ---------------------------------------------------------------------------
// Block-sparse causal attention (unchanged from the passing round-4 kernel).
// ---------------------------------------------------------------------------
#define SP 68

__global__ __launch_bounds__(128) void sparse_attn_kernel(const void* __restrict__ layout_raw)
{
    const int qb = blockIdx.x;
    const int h  = blockIdx.y;
    const int b  = blockIdx.z;

    const int t  = threadIdx.x;
    const int c  = t & 15;
    const int rp = t >> 4;
    const int r0 = rp * 2;
    const int r1 = rp * 2 + 1;
    const int c0 = c * 4;
    const int lanebase = t & 16;

    __shared__ float qs[16 * SP];
    __shared__ float ks[16 * SP];
    __shared__ float vs[16 * SP];

    const unsigned char* lb = (const unsigned char*)layout_raw;
    const bool is_u8 = (lb[128] != 0);
    const uint32_t* lw = (const uint32_t*)layout_raw;

    const float* base = g_qkv + (size_t)b * SEQ * INNER3;

    #pragma unroll
    for (int it = 0; it < 2; it++) {
        int f = t + it * 128;
        int row = f >> 4, cc = f & 15;
        float4 v = *(const float4*)(base + (size_t)(qb * BLK + row) * INNER3 + h * DH + cc * 4);
        *(float4*)(qs + row * SP + cc * 4) = v;
    }

    float m0 = -1e30f, l0 = 0.f, m1 = -1e30f, l1 = 0.f;
    float4 o0 = make_float4(0.f, 0.f, 0.f, 0.f);
    float4 o1 = make_float4(0.f, 0.f, 0.f, 0.f);
    const float scale = 0.125f;

    for (int jb = 0; jb <= qb; jb++) {
        bool allowed = is_u8 ? (lb[qb * NBLK + jb] != 0)
                             : (lw[qb * NBLK + jb] != 0u);
        if (!allowed) continue;

        __syncthreads();

        #pragma unroll
        for (int it = 0; it < 2; it++) {
            int f = t + it * 128;
            int row = f >> 4, cc = f & 15;
            const float* rowp = base + (size_t)(jb * BLK + row) * INNER3 + h * DH + cc * 4;
            *(float4*)(ks + row * SP + cc * 4) = *(const float4*)(rowp + DIM);
            *(float4*)(vs + row * SP + cc * 4) = *(const float4*)(rowp + 2 * DIM);
        }
        __syncthreads();

        float s0 = 0.f, s1 = 0.f;
        {
            const float4* kp = (const float4*)(ks + c  * SP);
            const float4* q0 = (const float4*)(qs + r0 * SP);
            const float4* q1 = (const float4*)(qs + r1 * SP);
            #pragma unroll
            for (int d = 0; d < 16; d++) {
                float4 kk = kp[d];
                float4 a0 = q0[d];
                float4 a1 = q1[d];
                s0 += a0.x * kk.x + a0.y * kk.y + a0.z * kk.z + a0.w * kk.w;
                s1 += a1.x * kk.x + a1.y * kk.y + a1.z * kk.z + a1.w * kk.w;
            }
        }
        s0 *= scale;
        s1 *= scale;
        if (jb == qb) {
            if (c > r0) s0 = -1e30f;
            if (c > r1) s1 = -1e30f;
        }

        float mr0 = s0, mr1 = s1;
        #pragma unroll
        for (int k = 1; k < 16; k <<= 1) {
            mr0 = fmaxf(mr0, __shfl_xor_sync(0xffffffffu, mr0, k, 32));
            mr1 = fmaxf(mr1, __shfl_xor_sync(0xffffffffu, mr1, k, 32));
        }
        float mn0 = fmaxf(m0, mr0);
        float mn1 = fmaxf(m1, mr1);
        float p0  = __expf(s0 - mn0);
        float p1  = __expf(s1 - mn1);
        float cr0 = __expf(m0 - mn0);
        float cr1 = __expf(m1 - mn1);

        float sm0 = p0, sm1 = p1;
        #pragma unroll
        for (int k = 1; k < 16; k <<= 1) {
            sm0 += __shfl_xor_sync(0xffffffffu, sm0, k, 32);
            sm1 += __shfl_xor_sync(0xffffffffu, sm1, k, 32);
        }
        l0 = l0 * cr0 + sm0;  m0 = mn0;
        l1 = l1 * cr1 + sm1;  m1 = mn1;
        o0.x *= cr0; o0.y *= cr0; o0.z *= cr0; o0.w *= cr0;
        o1.x *= cr1; o1.y *= cr1; o1.z *= cr1; o1.w *= cr1;

        #pragma unroll
        for (int j = 0; j < 16; j++) {
            float pj0 = __shfl_sync(0xffffffffu, p0, lanebase | j, 32);
            float pj1 = __shfl_sync(0xffffffffu, p1, lanebase | j, 32);
            float4 vv = *(const float4*)(vs + j * SP + c0);
            o0.x += pj0 * vv.x; o0.y += pj0 * vv.y; o0.z += pj0 * vv.z; o0.w += pj0 * vv.w;
            o1.x += pj1 * vv.x; o1.y += pj1 * vv.y; o1.z += pj1 * vv.z; o1.w += pj1 * vv.w;
        }
    }

    const float inv0 = 1.f / l0;
    const float inv1 = 1.f / l1;
    float* op0 = g_attn + (size_t)(b * SEQ + qb * BLK + r0) * DIM + h * DH + c0;
    float* op1 = g_attn + (size_t)(b * SEQ + qb * BLK + r1) * DIM + h * DH + c0;
    *(float4*)op0 = make_float4(o0.x * inv0, o0.y * inv0, o0.z * inv0, o0.w * inv0);
    *(float4*)op1 = make_float4(o1.x * inv1, o1.y * inv1, o1.z * inv1, o1.w * inv1);
}

// ---------------------------------------------------------------------------
// Inputs: 0:x [2,2048,1024] f32  1:w_qkv [1024,3072] f32
//         2:w_out [1024,1024] f32  3:b_out [1024] f32  4:layout [128,128] bool
// Output: [2,2048,1024] f32
// ---------------------------------------------------------------------------
extern "C" void kernel_launch(void* const* d_in, const int* in_sizes, int n_in,
                              void* d_out, int out_size)
{
    const float* x      = (const float*)d_in[0];
    const float* w_qkv  = (const float*)d_in[1];
    const float* w_out  = (const float*)d_in[2];
    const float* b_out  = (const float*)d_in[3];
    const void*  layout = d_in[4];
    float* out = (float*)d_out;

    cudaFuncSetAttribute(tc_gemm1_kernel,
                         cudaFuncAttributeMaxDynamicSharedMemorySize, SM_GEMM);
    cudaFuncSetAttribute(tc_gemm2_kernel,
                         cudaFuncAttributeMaxDynamicSharedMemorySize, SM_GEMM);

    // Prep: weight transposes + splits, x split
    {
        dim3 g1(INNER3 / 32, GK / 32);
        tsp_wq_kernel<<<g1, 256>>>(w_qkv);
        dim3 g2(DIM / 32, GK / 32);
        tsp_wo_kernel<<<g2, 256>>>(w_out);
        split_x_kernel<<<(BATCH * SEQ * DIM) / (256 * 4), 256>>>(x);
    }
    // 1) QKV projection (HMMA bf16-split): [4096,1024] @ [1024,3072] -> g_qkv
    {
        dim3 grid(INNER3 / 128, (BATCH * SEQ) / 128);
        tc_gemm1_kernel<<<grid, 256, SM_GEMM>>>();
    }
    // 2) Block-sparse causal attention -> g_attn
    {
        dim3 grid(NBLK, HEADS, BATCH);
        sparse_attn_kernel<<<grid, 128>>>(layout);
    }
    // 3) Split attn output, then output projection (HMMA) + bias -> out
    {
        split_attn_kernel<<<(BATCH * SEQ * DIM) / (256 * 4), 256>>>();
        dim3 grid(DIM / 128, (BATCH * SEQ) / 128);
        tc_gemm2_kernel<<<grid, 256, SM_GEMM>>>(b_out, out);
    }
}